// round 2
// baseline (speedup 1.0000x reference)
#include <cuda_runtime.h>
#include <cstdint>

// ROI bilinear pooling (TF1 resize_images semantics, align_corners=False).
// img:  (1024, 1024, 128) fp32, channels contiguous.
// rois: (512, 4) fp32 -> (x1, y1, w, h) integral values.
// out:  (512, 7, 7, 128) fp32.
//
// One warp per (roi, oy, ox): 32 lanes x float4 = 128 channels.
// Block (32,7) handles one (roi, oy) across all 7 ox. Grid (7, 512).

#define POOL 7
#define IMG_W 1024
#define IMG_H 1024
#define C4 32  // 128 channels / 4

__global__ __launch_bounds__(32 * POOL) void roi_pool_kernel(
    const float4* __restrict__ img,   // [1024][1024][32] float4
    const float4* __restrict__ rois,  // [512] float4 (x1,y1,w,h)
    float4* __restrict__ out)         // [512][7][7][32] float4
{
    const int roi = blockIdx.y;
    const int oy  = blockIdx.x;      // 0..6
    const int ox  = threadIdx.y;     // 0..6
    const int c   = threadIdx.x;     // 0..31 (float4 groups)

    const float4 r = rois[roi];
    const int x1 = (int)r.x;
    const int y1 = (int)r.y;
    const int w  = (int)r.z;
    const int h  = (int)r.w;

    // y axis coords (same fp32 ops as reference)
    const float sy   = (float)h / (float)POOL;
    const float srcy = (float)oy * sy;
    int ly = (int)floorf(srcy);
    ly = min(max(ly, 0), h - 1);
    const int hy = min(ly + 1, h - 1);
    const float fy = srcy - (float)ly;
    const int y_lo = min(max(y1 + ly, 0), IMG_H - 1);
    const int y_hi = min(max(y1 + hy, 0), IMG_H - 1);

    // x axis coords
    const float sx   = (float)w / (float)POOL;
    const float srcx = (float)ox * sx;
    int lx = (int)floorf(srcx);
    lx = min(max(lx, 0), w - 1);
    const int hx = min(lx + 1, w - 1);
    const float fx = srcx - (float)lx;
    const int x_lo = min(max(x1 + lx, 0), IMG_W - 1);
    const int x_hi = min(max(x1 + hx, 0), IMG_W - 1);

    // 4 coalesced 512B gathers (LDG.E.128 per lane)
    const size_t row_lo = (size_t)y_lo * IMG_W;
    const size_t row_hi = (size_t)y_hi * IMG_W;
    const float4 v00 = img[(row_lo + x_lo) * C4 + c];
    const float4 v01 = img[(row_lo + x_hi) * C4 + c];
    const float4 v10 = img[(row_hi + x_lo) * C4 + c];
    const float4 v11 = img[(row_hi + x_hi) * C4 + c];

    const float gx = 1.0f - fx;
    const float gy = 1.0f - fy;
    const float w00 = gy * gx;
    const float w01 = gy * fx;
    const float w10 = fy * gx;
    const float w11 = fy * fx;

    float4 o;
    o.x = v00.x * w00 + v01.x * w01 + v10.x * w10 + v11.x * w11;
    o.y = v00.y * w00 + v01.y * w01 + v10.y * w10 + v11.y * w11;
    o.z = v00.z * w00 + v01.z * w01 + v10.z * w10 + v11.z * w11;
    o.w = v00.w * w00 + v01.w * w01 + v10.w * w10 + v11.w * w11;

    out[(((size_t)roi * POOL + oy) * POOL + ox) * C4 + c] = o;
}

extern "C" void kernel_launch(void* const* d_in, const int* in_sizes, int n_in,
                              void* d_out, int out_size)
{
    const float4* img  = (const float4*)d_in[0];   // (1,1024,1024,128) fp32
    const float4* rois = (const float4*)d_in[1];   // (1,512,4) fp32
    float4* out = (float4*)d_out;                  // (1,512,7,7,128) fp32

    dim3 block(32, POOL);        // 224 threads: 7 warps, one per ox
    dim3 grid(POOL, 512);        // (oy, roi)
    roi_pool_kernel<<<grid, block>>>(img, rois, out);
}